// round 16
// baseline (speedup 1.0000x reference)
#include <cuda_runtime.h>
#include <cuda_bf16.h>
#include <math.h>

// ---------------- problem constants ----------------
#define Bc    32
#define Lc    64
#define Sc    64
#define SBc   2048
#define Dc    512
#define Hc    8
#define HDc   64
#define NLc   8
#define KCB   8192
#define Zc    32
#define DFFc  2048
#define D3c   1536
#define ROWSE 66560   // packed causal rows = 520*128

__host__ __device__ __forceinline__ size_t row_base(int s, int b) {
    return (size_t)16 * s * (s + 1) + (size_t)b * (s + 1);
}

// ---------------- scratch (device globals, no allocs) ----------------
__device__ float g_h  [(size_t)ROWSE * Dc];
__device__ float g_big[(size_t)ROWSE * D3c];
__device__ float g_bf [(size_t)ROWSE * Dc];
__device__ float g_ctx [(size_t)SBc * Dc];
__device__ float g_cav [(size_t)SBc * Dc];
__device__ int   g_idx [SBc];
__device__ int   g_rowsb[ROWSE];

__device__ __align__(16) __nv_bfloat16 g_hh[(size_t)ROWSE * Dc];
__device__ __align__(16) __nv_bfloat16 g_hl[(size_t)ROWSE * Dc];
__device__ __align__(16) __nv_bfloat16 g_ah[(size_t)ROWSE * Dc];
__device__ __align__(16) __nv_bfloat16 g_al[(size_t)ROWSE * Dc];
__device__ __align__(16) __nv_bfloat16 g_fh[(size_t)ROWSE * DFFc];
__device__ __align__(16) __nv_bfloat16 g_fl[(size_t)ROWSE * DFFc];
__device__ __align__(16) __nv_bfloat16 g_mh[(size_t)SBc * Dc];
__device__ __align__(16) __nv_bfloat16 g_ml[(size_t)SBc * Dc];
__device__ __align__(16) __nv_bfloat16 g_vh[(size_t)SBc * Dc];
__device__ __align__(16) __nv_bfloat16 g_vl[(size_t)SBc * Dc];
__device__ __align__(16) __nv_bfloat16 g_wh[1 << 20];
__device__ __align__(16) __nv_bfloat16 g_wl[1 << 20];

__device__ __forceinline__ void split2(float v, __nv_bfloat16& hi, __nv_bfloat16& lo) {
    hi = __float2bfloat16(v);
    lo = __float2bfloat16(v - __bfloat162float(hi));
}

// ---------------- PTX helpers ----------------
__device__ __forceinline__ void mma16816(float* c, const unsigned* a, const unsigned* b) {
    asm volatile(
        "mma.sync.aligned.m16n8k16.row.col.f32.bf16.bf16.f32 "
        "{%0,%1,%2,%3}, {%4,%5,%6,%7}, {%8,%9}, {%0,%1,%2,%3};"
        : "+f"(c[0]), "+f"(c[1]), "+f"(c[2]), "+f"(c[3])
        : "r"(a[0]), "r"(a[1]), "r"(a[2]), "r"(a[3]), "r"(b[0]), "r"(b[1]));
}
__device__ __forceinline__ void cpasync16(const __nv_bfloat16* s, const __nv_bfloat16* g) {
    unsigned sa = (unsigned)__cvta_generic_to_shared(s);
    asm volatile("cp.async.ca.shared.global [%0], [%1], 16;" :: "r"(sa), "l"(g));
}
__device__ __forceinline__ void cp_commit() { asm volatile("cp.async.commit_group;"); }
__device__ __forceinline__ void cp_wait0()  { asm volatile("cp.async.wait_group 0;"); }
__device__ __forceinline__ void ldsm4(unsigned* r, const __nv_bfloat16* p) {
    unsigned a = (unsigned)__cvta_generic_to_shared(p);
    asm volatile("ldmatrix.sync.aligned.m8n8.x4.shared.b16 {%0,%1,%2,%3}, [%4];"
                 : "=r"(r[0]), "=r"(r[1]), "=r"(r[2]), "=r"(r[3]) : "r"(a));
}
__device__ __forceinline__ void ldsm4t(unsigned* r, const __nv_bfloat16* p) {
    unsigned a = (unsigned)__cvta_generic_to_shared(p);
    asm volatile("ldmatrix.sync.aligned.m8n8.x4.trans.shared.b16 {%0,%1,%2,%3}, [%4];"
                 : "=r"(r[0]), "=r"(r[1]), "=r"(r[2]), "=r"(r[3]) : "r"(a));
}

// ---------------- bf16-pair tensor-core GEMM (cp.async + ldmatrix) ----------------
// C[M,N] = (Ah+Al)@(Wh+Wl) + bias ; 128x128x32 block tile, 8 warps (64x32 warp tile).
#define BK   32
#define ASTR 40    // A smem row stride (bf16)
#define BSTR 136   // B smem row stride (bf16)
#define SZA  (128 * ASTR)
#define SZB  (BK * BSTR)
#define GEMM_SMEM ((2 * 2 * SZA + 2 * 2 * SZB) * 2)   // 75776 bytes

__global__ __launch_bounds__(256) void mma_gemm_kernel(
    const __nv_bfloat16* __restrict__ Ah, const __nv_bfloat16* __restrict__ Al, int lda,
    const __nv_bfloat16* __restrict__ Wh, const __nv_bfloat16* __restrict__ Wl, int ldw,
    const float* __restrict__ bias,
    float* __restrict__ Cf,
    __nv_bfloat16* __restrict__ Ch, __nv_bfloat16* __restrict__ Cl,
    int ldc, int K, int relu)
{
    extern __shared__ __nv_bfloat16 smem[];
    __nv_bfloat16* sAh = smem;                 // [2][SZA]
    __nv_bfloat16* sAl = sAh + 2 * SZA;
    __nv_bfloat16* sBh = sAl + 2 * SZA;        // [2][SZB]
    __nv_bfloat16* sBl = sBh + 2 * SZB;

    const int tid  = threadIdx.x;
    const int warp = tid >> 5, lane = tid & 31;
    const int wm = warp & 1, wn = warp >> 1;
    const size_t rowBase = (size_t)blockIdx.y * 128;
    const int    colBase = blockIdx.x * 128;

    // loader chunk coords (2 chunks of 16B per array per thread per stage)
    const int c0 = tid * 2, c1 = tid * 2 + 1;
    const int ar0 = c0 >> 2, ac0 = (c0 & 3) * 8;
    const int ar1 = c1 >> 2, ac1 = (c1 & 3) * 8;
    const int br0 = c0 >> 4, bc0 = (c0 & 15) * 8;
    const int br1 = c1 >> 4, bc1 = (c1 & 15) * 8;
    const __nv_bfloat16* gAh0 = Ah + (rowBase + ar0) * (size_t)lda + ac0;
    const __nv_bfloat16* gAh1 = Ah + (rowBase + ar1) * (size_t)lda + ac1;
    const __nv_bfloat16* gAl0 = Al + (rowBase + ar0) * (size_t)lda + ac0;
    const __nv_bfloat16* gAl1 = Al + (rowBase + ar1) * (size_t)lda + ac1;
    const __nv_bfloat16* gBh0 = Wh + (size_t)br0 * ldw + colBase + bc0;
    const __nv_bfloat16* gBh1 = Wh + (size_t)br1 * ldw + colBase + bc1;
    const __nv_bfloat16* gBl0 = Wl + (size_t)br0 * ldw + colBase + bc0;
    const __nv_bfloat16* gBl1 = Wl + (size_t)br1 * ldw + colBase + bc1;
    const int sa0 = ar0 * ASTR + ac0, sa1 = ar1 * ASTR + ac1;
    const int sb0 = br0 * BSTR + bc0, sb1 = br1 * BSTR + bc1;

#define LOAD_STAGE(buf, k0)                                                     \
    do {                                                                        \
        cpasync16(sAh + (buf) * SZA + sa0, gAh0 + (k0));                        \
        cpasync16(sAh + (buf) * SZA + sa1, gAh1 + (k0));                        \
        cpasync16(sAl + (buf) * SZA + sa0, gAl0 + (k0));                        \
        cpasync16(sAl + (buf) * SZA + sa1, gAl1 + (k0));                        \
        cpasync16(sBh + (buf) * SZB + sb0, gBh0 + (size_t)(k0) * ldw);          \
        cpasync16(sBh + (buf) * SZB + sb1, gBh1 + (size_t)(k0) * ldw);          \
        cpasync16(sBl + (buf) * SZB + sb0, gBl0 + (size_t)(k0) * ldw);          \
        cpasync16(sBl + (buf) * SZB + sb1, gBl1 + (size_t)(k0) * ldw);          \
    } while (0)

    float acc[4][4][4];
#pragma unroll
    for (int i = 0; i < 4; i++)
#pragma unroll
        for (int j = 0; j < 4; j++)
#pragma unroll
            for (int r = 0; r < 4; r++) acc[i][j][r] = 0.f;

    // fragment lane addressing
    const int lm = lane >> 3;        // matrix id 0..3
    const int lr = lane & 7;         // row within matrix
    const int a_row_off = (lm & 1) * 8 + lr;
    const int a_col_off = (lm >> 1) * 8;
    const int b_k_off   = (lm & 1) * 8 + lr;
    const int b_n_off   = (lm >> 1) * 8;

    LOAD_STAGE(0, 0);
    cp_commit();
    cp_wait0();
    __syncthreads();

    int buf = 0;
    for (int k0 = 0; k0 < K; k0 += BK) {
        if (k0 + BK < K) { LOAD_STAGE(buf ^ 1, k0 + BK); cp_commit(); }

#pragma unroll
        for (int k16 = 0; k16 < BK; k16 += 16) {
            unsigned aH[4][4], aL[4][4], bH[4][2], bL[4][2];
#pragma unroll
            for (int mi = 0; mi < 4; mi++) {
                int off = (wm * 64 + mi * 16 + a_row_off) * ASTR + k16 + a_col_off;
                ldsm4(aH[mi], sAh + buf * SZA + off);
                ldsm4(aL[mi], sAl + buf * SZA + off);
            }
#pragma unroll
            for (int p = 0; p < 2; p++) {
                int off = (k16 + b_k_off) * BSTR + wn * 32 + p * 16 + b_n_off;
                unsigned t[4];
                ldsm4t(t, sBh + buf * SZB + off);
                bH[2 * p][0] = t[0]; bH[2 * p][1] = t[1];
                bH[2 * p + 1][0] = t[2]; bH[2 * p + 1][1] = t[3];
                ldsm4t(t, sBl + buf * SZB + off);
                bL[2 * p][0] = t[0]; bL[2 * p][1] = t[1];
                bL[2 * p + 1][0] = t[2]; bL[2 * p + 1][1] = t[3];
            }
#pragma unroll
            for (int mi = 0; mi < 4; mi++)
#pragma unroll
                for (int ni = 0; ni < 4; ni++) {
                    mma16816(acc[mi][ni], aH[mi], bH[ni]);
                    mma16816(acc[mi][ni], aH[mi], bL[ni]);
                    mma16816(acc[mi][ni], aL[mi], bH[ni]);
                }
        }

        if (k0 + BK < K) cp_wait0();
        __syncthreads();
        buf ^= 1;
    }

    // epilogue
    const int fr = lane >> 2;
    const int fc = (lane & 3) * 2;
#pragma unroll
    for (int mi = 0; mi < 4; mi++) {
#pragma unroll
        for (int ni = 0; ni < 4; ni++) {
            size_t row0 = rowBase + wm * 64 + mi * 16 + fr;
            size_t row1 = row0 + 8;
            int col0 = colBase + wn * 32 + ni * 8 + fc;
            float b0 = bias[col0], b1 = bias[col0 + 1];
            float v00 = acc[mi][ni][0] + b0;
            float v01 = acc[mi][ni][1] + b1;
            float v10 = acc[mi][ni][2] + b0;
            float v11 = acc[mi][ni][3] + b1;
            if (relu) {
                v00 = fmaxf(v00, 0.f); v01 = fmaxf(v01, 0.f);
                v10 = fmaxf(v10, 0.f); v11 = fmaxf(v11, 0.f);
            }
            if (Cf) {
                *reinterpret_cast<float2*>(Cf + row0 * ldc + col0) = make_float2(v00, v01);
                *reinterpret_cast<float2*>(Cf + row1 * ldc + col0) = make_float2(v10, v11);
            }
            if (Ch) {
                __nv_bfloat16 h0, l0, h1, l1;
                split2(v00, h0, l0); split2(v01, h1, l1);
                *reinterpret_cast<__nv_bfloat162*>(Ch + row0 * ldc + col0) =
                    __nv_bfloat162(h0, h1);
                *reinterpret_cast<__nv_bfloat162*>(Cl + row0 * ldc + col0) =
                    __nv_bfloat162(l0, l1);
                split2(v10, h0, l0); split2(v11, h1, l1);
                *reinterpret_cast<__nv_bfloat162*>(Ch + row1 * ldc + col0) =
                    __nv_bfloat162(h0, h1);
                *reinterpret_cast<__nv_bfloat162*>(Cl + row1 * ldc + col0) =
                    __nv_bfloat162(l0, l1);
            }
        }
    }
}

// ---------------- split fp32 -> bf16 pair (with optional column slice) ----------------
__global__ void split_kernel(const float* __restrict__ src, int srcld, int col0, int cols,
                             __nv_bfloat16* __restrict__ hi, __nv_bfloat16* __restrict__ lo)
{
    size_t idx = (size_t)blockIdx.x * 256 + threadIdx.x;
    int r = (int)(idx / cols), c = (int)(idx % cols);
    float v = src[(size_t)r * srcld + col0 + c];
    __nv_bfloat16 h, l;
    split2(v, h, l);
    hi[idx] = h; lo[idx] = l;
}

// ---------------- causal self-attention on packed rows ----------------
#define ATTN_SMEM 66048
__global__ void attn_kernel(const float* __restrict__ qkv,
                            __nv_bfloat16* __restrict__ oh, __nv_bfloat16* __restrict__ ol)
{
    extern __shared__ float sm[];
    float* Qs = sm;
    float* Ks = sm + 4160;
    float* Vs = sm + 8320;
    float* Ss = sm + 12416;
    const int sb = blockIdx.x;
    const int s  = sb >> 5;
    const int b  = sb & 31;
    const int n  = s + 1;
    const int head = blockIdx.y;
    const int tid = threadIdx.x;
    const size_t rowbase = row_base(s, b);
    const float* base = qkv + rowbase * D3c + head * HDc;

    for (int idx = tid; idx < n * HDc; idx += 256) {
        int l = idx >> 6, d = idx & 63;
        const float* p = base + (size_t)l * D3c;
        Qs[l * 65 + d] = p[d];
        Ks[l * 65 + d] = p[Dc + d];
        Vs[l * 64 + d] = p[2 * Dc + d];
    }
    __syncthreads();

    for (int e = tid; e < n * 64; e += 256) {
        int q = e >> 6, k = e & 63;
        float v = -1e9f;
        if (k < n) {
            float acc = 0.f;
#pragma unroll
            for (int d = 0; d < HDc; d++)
                acc = fmaf(Qs[q * 65 + d], Ks[k * 65 + d], acc);
            v = acc * 0.125f;
        }
        Ss[e] = v;
    }
    __syncthreads();

    const int warp = tid >> 5, lane = tid & 31;
    for (int q = warp; q < n; q += 8) {
        float v0 = Ss[q * 64 + lane];
        float v1 = Ss[q * 64 + 32 + lane];
        float m = fmaxf(v0, v1);
#pragma unroll
        for (int o = 16; o; o >>= 1) m = fmaxf(m, __shfl_xor_sync(0xffffffffu, m, o));
        float e0 = expf(v0 - m);
        float e1 = expf(v1 - m);
        float sum = e0 + e1;
#pragma unroll
        for (int o = 16; o; o >>= 1) sum += __shfl_xor_sync(0xffffffffu, sum, o);
        float inv = 1.f / sum;
        Ss[q * 64 + lane]      = e0 * inv;
        Ss[q * 64 + 32 + lane] = e1 * inv;
    }
    __syncthreads();

    for (int e = tid; e < n * HDc; e += 256) {
        int q = e >> 6, d = e & 63;
        float acc = 0.f;
        for (int k = 0; k < n; k++)
            acc = fmaf(Ss[q * 64 + k], Vs[k * 64 + d], acc);
        __nv_bfloat16 h, l;
        split2(acc, h, l);
        size_t o = (rowbase + q) * Dc + head * HDc + d;
        oh[o] = h; ol[o] = l;
    }
}

// ---------------- residual + LayerNorm (in place on h, emits bf16 pair) ----------------
__global__ void ln_kernel(float* __restrict__ h, const float* __restrict__ t,
                          const float* __restrict__ g, const float* __restrict__ bb,
                          const int* __restrict__ rowsb, int bcast,
                          __nv_bfloat16* __restrict__ hh, __nv_bfloat16* __restrict__ hl)
{
    __shared__ float red[8];
    const int r = blockIdx.x;
    const int tid = threadIdx.x;
    float* hr = h + (size_t)r * Dc;
    const float* tr = t + (size_t)(bcast ? rowsb[r] : r) * Dc;
    float x[4];
    float sum = 0.f;
#pragma unroll
    for (int i = 0; i < 4; i++) { x[i] = hr[tid + i * 128] + tr[tid + i * 128]; sum += x[i]; }
#pragma unroll
    for (int o = 16; o; o >>= 1) sum += __shfl_xor_sync(0xffffffffu, sum, o);
    if ((tid & 31) == 0) red[tid >> 5] = sum;
    __syncthreads();
    float mean = (red[0] + red[1] + red[2] + red[3]) * (1.f / 512.f);
    float vs = 0.f;
#pragma unroll
    for (int i = 0; i < 4; i++) { float d = x[i] - mean; vs = fmaf(d, d, vs); }
#pragma unroll
    for (int o = 16; o; o >>= 1) vs += __shfl_xor_sync(0xffffffffu, vs, o);
    if ((tid & 31) == 0) red[4 + (tid >> 5)] = vs;
    __syncthreads();
    float var = (red[4] + red[5] + red[6] + red[7]) * (1.f / 512.f);
    float inv = rsqrtf(var + 1e-5f);
#pragma unroll
    for (int i = 0; i < 4; i++) {
        float y = (x[i] - mean) * inv * g[tid + i * 128] + bb[tid + i * 128];
        hr[tid + i * 128] = y;
        __nv_bfloat16 yh, yl;
        split2(y, yh, yl);
        hh[(size_t)r * Dc + tid + i * 128] = yh;
        hl[(size_t)r * Dc + tid + i * 128] = yl;
    }
}

// ---------------- ctx_h0 = x_full[:, :L] @ W_in + b_in + PE ----------------
__global__ void build_ctx_kernel(const float* __restrict__ x,
                                 const float* __restrict__ Win, const float* __restrict__ bin,
                                 float* __restrict__ ctx)
{
    __shared__ float xv[32];
    const int r = blockIdx.x;
    const int b = r >> 6, l = r & 63;
    if (threadIdx.x < 32)
        xv[threadIdx.x] = (l == 0) ? 0.f : x[((size_t)b * Lc + (l - 1)) * Zc + threadIdx.x];
    __syncthreads();
    const float LOG1E4 = 9.210340371976184f;
    for (int d = threadIdx.x; d < Dc; d += 128) {
        float acc = bin[d];
#pragma unroll
        for (int z = 0; z < Zc; z++)
            acc = fmaf(xv[z], Win[z * Dc + d], acc);
        int d2 = d & ~1;
        float freq = expf(-LOG1E4 * (float)d2 * (1.f / 512.f));
        float ang = (float)l * freq;
        acc += (d & 1) ? cosf(ang) : sinf(ang);
        ctx[(size_t)r * Dc + d] = acc;
    }
}

// ---------------- VQ argmin over codebook ----------------
__global__ void vq_kernel(const float* __restrict__ x, const float* __restrict__ cb,
                          int* __restrict__ idx)
{
    __shared__ float mv[32];
    __shared__ float sd[256];
    __shared__ int   si[256];
    const int sb = blockIdx.x;
    const int s = sb >> 5, b = sb & 31;
    const int tid = threadIdx.x;
    if (tid < 32) mv[tid] = x[((size_t)b * Lc + s) * Zc + tid];
    __syncthreads();
    float bd = 3.4e38f; int bi = 0x7fffffff;
    for (int k = tid; k < KCB; k += 256) {
        const float* c = cb + (size_t)k * Zc;
        float d2 = 0.f;
#pragma unroll
        for (int z = 0; z < Zc; z++) { float df = mv[z] - c[z]; d2 = fmaf(df, df, d2); }
        if (d2 < bd || (d2 == bd && k < bi)) { bd = d2; bi = k; }
    }
    sd[tid] = bd; si[tid] = bi;
    __syncthreads();
    for (int off = 128; off; off >>= 1) {
        if (tid < off) {
            if (sd[tid + off] < sd[tid] ||
                (sd[tid + off] == sd[tid] && si[tid + off] < si[tid])) {
                sd[tid] = sd[tid + off]; si[tid] = si[tid + off];
            }
        }
        __syncthreads();
    }
    if (tid == 0) idx[sb] = si[0];
}

// ---------------- mem_h = codebook[idx] @ W_in + b_in  (bf16 pair out) ----------------
__global__ void build_memh_kernel(const float* __restrict__ cb, const int* __restrict__ idx,
                                  const float* __restrict__ Win, const float* __restrict__ bin,
                                  __nv_bfloat16* __restrict__ mh, __nv_bfloat16* __restrict__ ml)
{
    __shared__ float qv[32];
    const int sb = blockIdx.x;
    if (threadIdx.x < 32)
        qv[threadIdx.x] = cb[(size_t)idx[sb] * Zc + threadIdx.x];
    __syncthreads();
    for (int d = threadIdx.x; d < Dc; d += 128) {
        float acc = bin[d];
#pragma unroll
        for (int z = 0; z < Zc; z++)
            acc = fmaf(qv[z], Win[z * Dc + d], acc);
        __nv_bfloat16 h, l;
        split2(acc, h, l);
        mh[(size_t)sb * Dc + d] = h;
        ml[(size_t)sb * Dc + d] = l;
    }
}

// ---------------- init packed h from ctx + row->sb map + bf16 pair ----------------
__global__ void build_h_kernel(const float* __restrict__ ctx, float* __restrict__ h,
                               int* __restrict__ rowsb,
                               __nv_bfloat16* __restrict__ hh, __nv_bfloat16* __restrict__ hl)
{
    const int sb = blockIdx.x;
    const int s = sb >> 5, b = sb & 31;
    const int n = s + 1;
    const size_t base = row_base(s, b);
    const float* src = ctx + ((size_t)b * Lc) * Dc;
    float* dst = h + base * Dc;
    const int tot = n * Dc;
    for (int i = threadIdx.x; i < tot; i += 256) {
        float v = src[i];
        dst[i] = v;
        __nv_bfloat16 vh, vl;
        split2(v, vh, vl);
        hh[base * Dc + i] = vh;
        hl[base * Dc + i] = vl;
    }
    for (int l = threadIdx.x; l < n; l += 256)
        rowsb[base + l] = sb;
}

// ---------------- final readout ----------------
__global__ void final_kernel(const float* __restrict__ h,
                             const float* __restrict__ g, const float* __restrict__ bb,
                             const float* __restrict__ Wout, const float* __restrict__ bout,
                             float* __restrict__ out)
{
    __shared__ float red[8];
    __shared__ float tv[512];
    __shared__ float part[128];
    const int sb = blockIdx.x;
    const int s = sb >> 5, b = sb & 31;
    const int tid = threadIdx.x;
    const float* hr = h + (row_base(s, b) + s) * Dc;
    float x[4]; float sum = 0.f;
#pragma unroll
    for (int i = 0; i < 4; i++) { x[i] = hr[tid + i * 128]; sum += x[i]; }
#pragma unroll
    for (int o = 16; o; o >>= 1) sum += __shfl_xor_sync(0xffffffffu, sum, o);
    if ((tid & 31) == 0) red[tid >> 5] = sum;
    __syncthreads();
    float mean = (red[0] + red[1] + red[2] + red[3]) * (1.f / 512.f);
    float vs = 0.f;
#pragma unroll
    for (int i = 0; i < 4; i++) { float d = x[i] - mean; vs = fmaf(d, d, vs); }
#pragma unroll
    for (int o = 16; o; o >>= 1) vs += __shfl_xor_sync(0xffffffffu, vs, o);
    if ((tid & 31) == 0) red[4 + (tid >> 5)] = vs;
    __syncthreads();
    float var = (red[4] + red[5] + red[6] + red[7]) * (1.f / 512.f);
    float inv = rsqrtf(var + 1e-5f);
#pragma unroll
    for (int i = 0; i < 4; i++)
        tv[tid + i * 128] = (x[i] - mean) * inv * g[tid + i * 128] + bb[tid + i * 128];
    __syncthreads();
    const int z = tid & 31, c = tid >> 5;
    float acc = 0.f;
    for (int k = c * 128; k < c * 128 + 128; k++)
        acc = fmaf(tv[k], Wout[(size_t)k * Zc + z], acc);
    part[tid] = acc;
    __syncthreads();
    if (tid < 32)
        out[((size_t)b * Lc + s) * Zc + z] =
            part[z] + part[32 + z] + part[64 + z] + part[96 + z] + bout[z];
}

// ---------------- host helpers ----------------
static __nv_bfloat16 *s_wh, *s_wl;

static inline void wsplit(const float* W, int ldw, int col0, int rows, int cols)
{
    split_kernel<<<(rows * cols) / 256, 256>>>(W, ldw, col0, cols, s_wh, s_wl);
}

static inline void gemm(const __nv_bfloat16* Ah, const __nv_bfloat16* Al, int lda,
                        const float* bias, float* Cf,
                        __nv_bfloat16* Ch, __nv_bfloat16* Cl,
                        int ldc, int M, int N, int K, int relu)
{
    dim3 grid(N / 128, M / 128);
    mma_gemm_kernel<<<grid, 256, GEMM_SMEM>>>(Ah, Al, lda, s_wh, s_wl, N, bias,
                                              Cf, Ch, Cl, ldc, K, relu);
}

extern "C" void kernel_launch(void* const* d_in, const int* in_sizes, int n_in,
                              void* d_out, int out_size)
{
    const float* x        = (const float*)d_in[0];
    const float* codebook = (const float*)d_in[1];
    const float* W_in     = (const float*)d_in[2];
    const float* b_in     = (const float*)d_in[3];
    const float* sa_qkv_w = (const float*)d_in[4];
    const float* sa_qkv_b = (const float*)d_in[5];
    const float* sa_out_w = (const float*)d_in[6];
    const float* sa_out_b = (const float*)d_in[7];
    const float* ca_qkv_w = (const float*)d_in[8];
    const float* ca_qkv_b = (const float*)d_in[9];
    const float* ca_out_w = (const float*)d_in[10];
    const float* ca_out_b = (const float*)d_in[11];
    const float* ff1_w    = (const float*)d_in[12];
    const float* ff1_b    = (const float*)d_in[13];
    const float* ff2_w    = (const float*)d_in[14];
    const float* ff2_b    = (const float*)d_in[15];
    const float* ln1_g    = (const float*)d_in[16];
    const float* ln1_b    = (const float*)d_in[17];
    const float* ln2_g    = (const float*)d_in[18];
    const float* ln2_b    = (const float*)d_in[19];
    const float* ln3_g    = (const float*)d_in[20];
    const float* ln3_b    = (const float*)d_in[21];
    const float* ln_g     = (const float*)d_in[22];
    const float* ln_b     = (const float*)d_in[23];
    const float* W_out    = (const float*)d_in[24];
    const float* b_out    = (const float*)d_in[25];
    float* out = (float*)d_out;

    float *h, *big, *bf, *ctx, *cav; int *idx, *rowsb;
    __nv_bfloat16 *hh, *hl, *ah, *al, *fh, *fl, *mh, *ml, *vh, *vl;
    cudaGetSymbolAddress((void**)&h,    g_h);
    cudaGetSymbolAddress((void**)&big,  g_big);
    cudaGetSymbolAddress((void**)&bf,   g_bf);
    cudaGetSymbolAddress((void**)&ctx,  g_ctx);
    cudaGetSymbolAddress((void**)&cav,  g_cav);
    cudaGetSymbolAddress((void**)&idx,  g_idx);
    cudaGetSymbolAddress((void**)&rowsb, g_rowsb);
    cudaGetSymbolAddress((void**)&hh, g_hh);
    cudaGetSymbolAddress((void**)&hl, g_hl);
    cudaGetSymbolAddress((void**)&ah, g_ah);
    cudaGetSymbolAddress((void**)&al, g_al);
    cudaGetSymbolAddress((void**)&fh, g_fh);
    cudaGetSymbolAddress((void**)&fl, g_fl);
    cudaGetSymbolAddress((void**)&mh, g_mh);
    cudaGetSymbolAddress((void**)&ml, g_ml);
    cudaGetSymbolAddress((void**)&vh, g_vh);
    cudaGetSymbolAddress((void**)&vl, g_vl);
    cudaGetSymbolAddress((void**)&s_wh, g_wh);
    cudaGetSymbolAddress((void**)&s_wl, g_wl);

    cudaFuncSetAttribute(attn_kernel, cudaFuncAttributeMaxDynamicSharedMemorySize, ATTN_SMEM);
    cudaFuncSetAttribute(mma_gemm_kernel, cudaFuncAttributeMaxDynamicSharedMemorySize, GEMM_SMEM);

    build_ctx_kernel<<<SBc, 128>>>(x, W_in, b_in, ctx);
    vq_kernel<<<SBc, 256>>>(x, codebook, idx);
    build_memh_kernel<<<SBc, 128>>>(codebook, idx, W_in, b_in, mh, ml);
    build_h_kernel<<<SBc, 256>>>(ctx, h, rowsb, hh, hl);

    for (int l = 0; l < NLc; l++) {
        // --- self-attention ---
        wsplit(sa_qkv_w + (size_t)l * Dc * D3c, D3c, 0, Dc, D3c);
        gemm(hh, hl, Dc, sa_qkv_b + (size_t)l * D3c, big, 0, 0, D3c, ROWSE, D3c, Dc, 0);
        attn_kernel<<<dim3(SBc, Hc), 256, ATTN_SMEM>>>(big, ah, al);
        wsplit(sa_out_w + (size_t)l * Dc * Dc, Dc, 0, Dc, Dc);
        gemm(ah, al, Dc, sa_out_b + (size_t)l * Dc, bf, 0, 0, Dc, ROWSE, Dc, Dc, 0);
        ln_kernel<<<ROWSE, 128>>>(h, bf, ln1_g + (size_t)l * Dc, ln1_b + (size_t)l * Dc,
                                  rowsb, 0, hh, hl);

        // --- cross-attention: softmax over 1 key == identity -> value path only ---
        wsplit(ca_qkv_w + (size_t)l * Dc * D3c, D3c, 2 * Dc, Dc, Dc);
        gemm(mh, ml, Dc, ca_qkv_b + (size_t)l * D3c + 2 * Dc, 0, vh, vl, Dc, SBc, Dc, Dc, 0);
        wsplit(ca_out_w + (size_t)l * Dc * Dc, Dc, 0, Dc, Dc);
        gemm(vh, vl, Dc, ca_out_b + (size_t)l * Dc, cav, 0, 0, Dc, SBc, Dc, Dc, 0);
        ln_kernel<<<ROWSE, 128>>>(h, cav, ln2_g + (size_t)l * Dc, ln2_b + (size_t)l * Dc,
                                  rowsb, 1, hh, hl);

        // --- FFN ---
        wsplit(ff1_w + (size_t)l * Dc * DFFc, DFFc, 0, Dc, DFFc);
        gemm(hh, hl, Dc, ff1_b + (size_t)l * DFFc, 0, fh, fl, DFFc, ROWSE, DFFc, Dc, 1);
        wsplit(ff2_w + (size_t)l * DFFc * Dc, Dc, 0, DFFc, Dc);
        gemm(fh, fl, DFFc, ff2_b + (size_t)l * Dc, bf, 0, 0, Dc, ROWSE, Dc, DFFc, 0);
        ln_kernel<<<ROWSE, 128>>>(h, bf, ln3_g + (size_t)l * Dc, ln3_b + (size_t)l * Dc,
                                  rowsb, 0, hh, hl);
    }

    final_kernel<<<SBc, 128>>>(h, ln_g, ln_b, W_out, b_out, out);
}

// round 17
// speedup vs baseline: 1.0003x; 1.0003x over previous
#include <cuda_runtime.h>
#include <cuda_bf16.h>
#include <math.h>

// ---------------- problem constants ----------------
#define Bc    32
#define Lc    64
#define Sc    64
#define SBc   2048
#define Dc    512
#define Hc    8
#define HDc   64
#define NLc   8
#define KCB   8192
#define Zc    32
#define DFFc  2048
#define D3c   1536
#define ROWSE 66560   // packed causal rows = 520*128

__host__ __device__ __forceinline__ size_t row_base(int s, int b) {
    return (size_t)16 * s * (s + 1) + (size_t)b * (s + 1);
}

// ---------------- scratch (device globals, no allocs) ----------------
__device__ float g_h  [(size_t)ROWSE * Dc];
__device__ float g_big[(size_t)ROWSE * D3c];
__device__ float g_bf [(size_t)ROWSE * Dc];
__device__ float g_ctx [(size_t)SBc * Dc];
__device__ float g_cav [(size_t)SBc * Dc];
__device__ int   g_idx [SBc];
__device__ int   g_rowsb[ROWSE];

__device__ __align__(16) __nv_bfloat16 g_hh[(size_t)ROWSE * Dc];
__device__ __align__(16) __nv_bfloat16 g_hl[(size_t)ROWSE * Dc];
__device__ __align__(16) __nv_bfloat16 g_ah[(size_t)ROWSE * Dc];
__device__ __align__(16) __nv_bfloat16 g_al[(size_t)ROWSE * Dc];
__device__ __align__(16) __nv_bfloat16 g_fh[(size_t)ROWSE * DFFc];
__device__ __align__(16) __nv_bfloat16 g_fl[(size_t)ROWSE * DFFc];
__device__ __align__(16) __nv_bfloat16 g_mh[(size_t)SBc * Dc];
__device__ __align__(16) __nv_bfloat16 g_ml[(size_t)SBc * Dc];
__device__ __align__(16) __nv_bfloat16 g_vh[(size_t)SBc * Dc];
__device__ __align__(16) __nv_bfloat16 g_vl[(size_t)SBc * Dc];
__device__ __align__(16) __nv_bfloat16 g_wh[1 << 20];
__device__ __align__(16) __nv_bfloat16 g_wl[1 << 20];

__device__ __forceinline__ void split2(float v, __nv_bfloat16& hi, __nv_bfloat16& lo) {
    hi = __float2bfloat16(v);
    lo = __float2bfloat16(v - __bfloat162float(hi));
}

// ---------------- PTX helpers ----------------
__device__ __forceinline__ void mma16816(float* c, const unsigned* a, const unsigned* b) {
    asm volatile(
        "mma.sync.aligned.m16n8k16.row.col.f32.bf16.bf16.f32 "
        "{%0,%1,%2,%3}, {%4,%5,%6,%7}, {%8,%9}, {%0,%1,%2,%3};"
        : "+f"(c[0]), "+f"(c[1]), "+f"(c[2]), "+f"(c[3])
        : "r"(a[0]), "r"(a[1]), "r"(a[2]), "r"(a[3]), "r"(b[0]), "r"(b[1]));
}
__device__ __forceinline__ void cpasync16(const __nv_bfloat16* s, const __nv_bfloat16* g) {
    unsigned sa = (unsigned)__cvta_generic_to_shared(s);
    asm volatile("cp.async.ca.shared.global [%0], [%1], 16;" :: "r"(sa), "l"(g));
}
__device__ __forceinline__ void cp_commit() { asm volatile("cp.async.commit_group;"); }
__device__ __forceinline__ void cp_wait0()  { asm volatile("cp.async.wait_group 0;"); }
__device__ __forceinline__ void ldsm4(unsigned* r, const __nv_bfloat16* p) {
    unsigned a = (unsigned)__cvta_generic_to_shared(p);
    asm volatile("ldmatrix.sync.aligned.m8n8.x4.shared.b16 {%0,%1,%2,%3}, [%4];"
                 : "=r"(r[0]), "=r"(r[1]), "=r"(r[2]), "=r"(r[3]) : "r"(a));
}
__device__ __forceinline__ void ldsm4t(unsigned* r, const __nv_bfloat16* p) {
    unsigned a = (unsigned)__cvta_generic_to_shared(p);
    asm volatile("ldmatrix.sync.aligned.m8n8.x4.trans.shared.b16 {%0,%1,%2,%3}, [%4];"
                 : "=r"(r[0]), "=r"(r[1]), "=r"(r[2]), "=r"(r[3]) : "r"(a));
}

// ---------------- bf16-pair tensor-core GEMM (cp.async + ldmatrix) ----------------
// C[M,N] = (Ah+Al)@(Wh+Wl) + bias ; 128x128x32 block tile, 8 warps (64x32 warp tile).
#define BK   32
#define ASTR 40    // A smem row stride (bf16)
#define BSTR 136   // B smem row stride (bf16)
#define SZA  (128 * ASTR)
#define SZB  (BK * BSTR)
#define GEMM_SMEM ((2 * 2 * SZA + 2 * 2 * SZB) * 2)   // 75776 bytes

__global__ __launch_bounds__(256) void mma_gemm_kernel(
    const __nv_bfloat16* __restrict__ Ah, const __nv_bfloat16* __restrict__ Al, int lda,
    const __nv_bfloat16* __restrict__ Wh, const __nv_bfloat16* __restrict__ Wl, int ldw,
    const float* __restrict__ bias,
    float* __restrict__ Cf,
    __nv_bfloat16* __restrict__ Ch, __nv_bfloat16* __restrict__ Cl,
    int ldc, int K, int relu)
{
    extern __shared__ __nv_bfloat16 smem[];
    __nv_bfloat16* sAh = smem;                 // [2][SZA]
    __nv_bfloat16* sAl = sAh + 2 * SZA;
    __nv_bfloat16* sBh = sAl + 2 * SZA;        // [2][SZB]
    __nv_bfloat16* sBl = sBh + 2 * SZB;

    const int tid  = threadIdx.x;
    const int warp = tid >> 5, lane = tid & 31;
    const int wm = warp & 1, wn = warp >> 1;
    const size_t rowBase = (size_t)blockIdx.y * 128;
    const int    colBase = blockIdx.x * 128;

    // loader chunk coords (2 chunks of 16B per array per thread per stage)
    const int c0 = tid * 2, c1 = tid * 2 + 1;
    const int ar0 = c0 >> 2, ac0 = (c0 & 3) * 8;
    const int ar1 = c1 >> 2, ac1 = (c1 & 3) * 8;
    const int br0 = c0 >> 4, bc0 = (c0 & 15) * 8;
    const int br1 = c1 >> 4, bc1 = (c1 & 15) * 8;
    const __nv_bfloat16* gAh0 = Ah + (rowBase + ar0) * (size_t)lda + ac0;
    const __nv_bfloat16* gAh1 = Ah + (rowBase + ar1) * (size_t)lda + ac1;
    const __nv_bfloat16* gAl0 = Al + (rowBase + ar0) * (size_t)lda + ac0;
    const __nv_bfloat16* gAl1 = Al + (rowBase + ar1) * (size_t)lda + ac1;
    const __nv_bfloat16* gBh0 = Wh + (size_t)br0 * ldw + colBase + bc0;
    const __nv_bfloat16* gBh1 = Wh + (size_t)br1 * ldw + colBase + bc1;
    const __nv_bfloat16* gBl0 = Wl + (size_t)br0 * ldw + colBase + bc0;
    const __nv_bfloat16* gBl1 = Wl + (size_t)br1 * ldw + colBase + bc1;
    const int sa0 = ar0 * ASTR + ac0, sa1 = ar1 * ASTR + ac1;
    const int sb0 = br0 * BSTR + bc0, sb1 = br1 * BSTR + bc1;

#define LOAD_STAGE(buf, k0)                                                     \
    do {                                                                        \
        cpasync16(sAh + (buf) * SZA + sa0, gAh0 + (k0));                        \
        cpasync16(sAh + (buf) * SZA + sa1, gAh1 + (k0));                        \
        cpasync16(sAl + (buf) * SZA + sa0, gAl0 + (k0));                        \
        cpasync16(sAl + (buf) * SZA + sa1, gAl1 + (k0));                        \
        cpasync16(sBh + (buf) * SZB + sb0, gBh0 + (size_t)(k0) * ldw);          \
        cpasync16(sBh + (buf) * SZB + sb1, gBh1 + (size_t)(k0) * ldw);          \
        cpasync16(sBl + (buf) * SZB + sb0, gBl0 + (size_t)(k0) * ldw);          \
        cpasync16(sBl + (buf) * SZB + sb1, gBl1 + (size_t)(k0) * ldw);          \
    } while (0)

    float acc[4][4][4];
#pragma unroll
    for (int i = 0; i < 4; i++)
#pragma unroll
        for (int j = 0; j < 4; j++)
#pragma unroll
            for (int r = 0; r < 4; r++) acc[i][j][r] = 0.f;

    // fragment lane addressing
    const int lm = lane >> 3;        // matrix id 0..3
    const int lr = lane & 7;         // row within matrix
    const int a_row_off = (lm & 1) * 8 + lr;
    const int a_col_off = (lm >> 1) * 8;
    const int b_k_off   = (lm & 1) * 8 + lr;
    const int b_n_off   = (lm >> 1) * 8;

    LOAD_STAGE(0, 0);
    cp_commit();
    cp_wait0();
    __syncthreads();

    int buf = 0;
    for (int k0 = 0; k0 < K; k0 += BK) {
        if (k0 + BK < K) { LOAD_STAGE(buf ^ 1, k0 + BK); cp_commit(); }

#pragma unroll
        for (int k16 = 0; k16 < BK; k16 += 16) {
            unsigned aH[4][4], aL[4][4], bH[4][2], bL[4][2];
#pragma unroll
            for (int mi = 0; mi < 4; mi++) {
                int off = (wm * 64 + mi * 16 + a_row_off) * ASTR + k16 + a_col_off;
                ldsm4(aH[mi], sAh + buf * SZA + off);
                ldsm4(aL[mi], sAl + buf * SZA + off);
            }
#pragma unroll
            for (int p = 0; p < 2; p++) {
                int off = (k16 + b_k_off) * BSTR + wn * 32 + p * 16 + b_n_off;
                unsigned t[4];
                ldsm4t(t, sBh + buf * SZB + off);
                bH[2 * p][0] = t[0]; bH[2 * p][1] = t[1];
                bH[2 * p + 1][0] = t[2]; bH[2 * p + 1][1] = t[3];
                ldsm4t(t, sBl + buf * SZB + off);
                bL[2 * p][0] = t[0]; bL[2 * p][1] = t[1];
                bL[2 * p + 1][0] = t[2]; bL[2 * p + 1][1] = t[3];
            }
#pragma unroll
            for (int mi = 0; mi < 4; mi++)
#pragma unroll
                for (int ni = 0; ni < 4; ni++) {
                    mma16816(acc[mi][ni], aH[mi], bH[ni]);
                    mma16816(acc[mi][ni], aH[mi], bL[ni]);
                    mma16816(acc[mi][ni], aL[mi], bH[ni]);
                }
        }

        if (k0 + BK < K) cp_wait0();
        __syncthreads();
        buf ^= 1;
    }

    // epilogue
    const int fr = lane >> 2;
    const int fc = (lane & 3) * 2;
#pragma unroll
    for (int mi = 0; mi < 4; mi++) {
#pragma unroll
        for (int ni = 0; ni < 4; ni++) {
            size_t row0 = rowBase + wm * 64 + mi * 16 + fr;
            size_t row1 = row0 + 8;
            int col0 = colBase + wn * 32 + ni * 8 + fc;
            float b0 = bias[col0], b1 = bias[col0 + 1];
            float v00 = acc[mi][ni][0] + b0;
            float v01 = acc[mi][ni][1] + b1;
            float v10 = acc[mi][ni][2] + b0;
            float v11 = acc[mi][ni][3] + b1;
            if (relu) {
                v00 = fmaxf(v00, 0.f); v01 = fmaxf(v01, 0.f);
                v10 = fmaxf(v10, 0.f); v11 = fmaxf(v11, 0.f);
            }
            if (Cf) {
                *reinterpret_cast<float2*>(Cf + row0 * ldc + col0) = make_float2(v00, v01);
                *reinterpret_cast<float2*>(Cf + row1 * ldc + col0) = make_float2(v10, v11);
            }
            if (Ch) {
                __nv_bfloat16 h0, l0, h1, l1;
                split2(v00, h0, l0); split2(v01, h1, l1);
                *reinterpret_cast<__nv_bfloat162*>(Ch + row0 * ldc + col0) =
                    __nv_bfloat162(h0, h1);
                *reinterpret_cast<__nv_bfloat162*>(Cl + row0 * ldc + col0) =
                    __nv_bfloat162(l0, l1);
                split2(v10, h0, l0); split2(v11, h1, l1);
                *reinterpret_cast<__nv_bfloat162*>(Ch + row1 * ldc + col0) =
                    __nv_bfloat162(h0, h1);
                *reinterpret_cast<__nv_bfloat162*>(Cl + row1 * ldc + col0) =
                    __nv_bfloat162(l0, l1);
            }
        }
    }
}

// ---------------- split fp32 -> bf16 pair (with optional column slice) ----------------
__global__ void split_kernel(const float* __restrict__ src, int srcld, int col0, int cols,
                             __nv_bfloat16* __restrict__ hi, __nv_bfloat16* __restrict__ lo)
{
    size_t idx = (size_t)blockIdx.x * 256 + threadIdx.x;
    int r = (int)(idx / cols), c = (int)(idx % cols);
    float v = src[(size_t)r * srcld + col0 + c];
    __nv_bfloat16 h, l;
    split2(v, h, l);
    hi[idx] = h; lo[idx] = l;
}

// ---------------- causal self-attention on packed rows ----------------
#define ATTN_SMEM 66048
__global__ void attn_kernel(const float* __restrict__ qkv,
                            __nv_bfloat16* __restrict__ oh, __nv_bfloat16* __restrict__ ol)
{
    extern __shared__ float sm[];
    float* Qs = sm;
    float* Ks = sm + 4160;
    float* Vs = sm + 8320;
    float* Ss = sm + 12416;
    const int sb = blockIdx.x;
    const int s  = sb >> 5;
    const int b  = sb & 31;
    const int n  = s + 1;
    const int head = blockIdx.y;
    const int tid = threadIdx.x;
    const size_t rowbase = row_base(s, b);
    const float* base = qkv + rowbase * D3c + head * HDc;

    for (int idx = tid; idx < n * HDc; idx += 256) {
        int l = idx >> 6, d = idx & 63;
        const float* p = base + (size_t)l * D3c;
        Qs[l * 65 + d] = p[d];
        Ks[l * 65 + d] = p[Dc + d];
        Vs[l * 64 + d] = p[2 * Dc + d];
    }
    __syncthreads();

    for (int e = tid; e < n * 64; e += 256) {
        int q = e >> 6, k = e & 63;
        float v = -1e9f;
        if (k < n) {
            float acc = 0.f;
#pragma unroll
            for (int d = 0; d < HDc; d++)
                acc = fmaf(Qs[q * 65 + d], Ks[k * 65 + d], acc);
            v = acc * 0.125f;
        }
        Ss[e] = v;
    }
    __syncthreads();

    const int warp = tid >> 5, lane = tid & 31;
    for (int q = warp; q < n; q += 8) {
        float v0 = Ss[q * 64 + lane];
        float v1 = Ss[q * 64 + 32 + lane];
        float m = fmaxf(v0, v1);
#pragma unroll
        for (int o = 16; o; o >>= 1) m = fmaxf(m, __shfl_xor_sync(0xffffffffu, m, o));
        float e0 = expf(v0 - m);
        float e1 = expf(v1 - m);
        float sum = e0 + e1;
#pragma unroll
        for (int o = 16; o; o >>= 1) sum += __shfl_xor_sync(0xffffffffu, sum, o);
        float inv = 1.f / sum;
        Ss[q * 64 + lane]      = e0 * inv;
        Ss[q * 64 + 32 + lane] = e1 * inv;
    }
    __syncthreads();

    for (int e = tid; e < n * HDc; e += 256) {
        int q = e >> 6, d = e & 63;
        float acc = 0.f;
        for (int k = 0; k < n; k++)
            acc = fmaf(Ss[q * 64 + k], Vs[k * 64 + d], acc);
        __nv_bfloat16 h, l;
        split2(acc, h, l);
        size_t o = (rowbase + q) * Dc + head * HDc + d;
        oh[o] = h; ol[o] = l;
    }
}

// ---------------- residual + LayerNorm (in place on h, emits bf16 pair) ----------------
__global__ void ln_kernel(float* __restrict__ h, const float* __restrict__ t,
                          const float* __restrict__ g, const float* __restrict__ bb,
                          const int* __restrict__ rowsb, int bcast,
                          __nv_bfloat16* __restrict__ hh, __nv_bfloat16* __restrict__ hl)
{
    __shared__ float red[8];
    const int r = blockIdx.x;
    const int tid = threadIdx.x;
    float* hr = h + (size_t)r * Dc;
    const float* tr = t + (size_t)(bcast ? rowsb[r] : r) * Dc;
    float x[4];
    float sum = 0.f;
#pragma unroll
    for (int i = 0; i < 4; i++) { x[i] = hr[tid + i * 128] + tr[tid + i * 128]; sum += x[i]; }
#pragma unroll
    for (int o = 16; o; o >>= 1) sum += __shfl_xor_sync(0xffffffffu, sum, o);
    if ((tid & 31) == 0) red[tid >> 5] = sum;
    __syncthreads();
    float mean = (red[0] + red[1] + red[2] + red[3]) * (1.f / 512.f);
    float vs = 0.f;
#pragma unroll
    for (int i = 0; i < 4; i++) { float d = x[i] - mean; vs = fmaf(d, d, vs); }
#pragma unroll
    for (int o = 16; o; o >>= 1) vs += __shfl_xor_sync(0xffffffffu, vs, o);
    if ((tid & 31) == 0) red[4 + (tid >> 5)] = vs;
    __syncthreads();
    float var = (red[4] + red[5] + red[6] + red[7]) * (1.f / 512.f);
    float inv = rsqrtf(var + 1e-5f);
#pragma unroll
    for (int i = 0; i < 4; i++) {
        float y = (x[i] - mean) * inv * g[tid + i * 128] + bb[tid + i * 128];
        hr[tid + i * 128] = y;
        __nv_bfloat16 yh, yl;
        split2(y, yh, yl);
        hh[(size_t)r * Dc + tid + i * 128] = yh;
        hl[(size_t)r * Dc + tid + i * 128] = yl;
    }
}

// ---------------- ctx_h0 = x_full[:, :L] @ W_in + b_in + PE ----------------
__global__ void build_ctx_kernel(const float* __restrict__ x,
                                 const float* __restrict__ Win, const float* __restrict__ bin,
                                 float* __restrict__ ctx)
{
    __shared__ float xv[32];
    const int r = blockIdx.x;
    const int b = r >> 6, l = r & 63;
    if (threadIdx.x < 32)
        xv[threadIdx.x] = (l == 0) ? 0.f : x[((size_t)b * Lc + (l - 1)) * Zc + threadIdx.x];
    __syncthreads();
    const float LOG1E4 = 9.210340371976184f;
    for (int d = threadIdx.x; d < Dc; d += 128) {
        float acc = bin[d];
#pragma unroll
        for (int z = 0; z < Zc; z++)
            acc = fmaf(xv[z], Win[z * Dc + d], acc);
        int d2 = d & ~1;
        float freq = expf(-LOG1E4 * (float)d2 * (1.f / 512.f));
        float ang = (float)l * freq;
        acc += (d & 1) ? cosf(ang) : sinf(ang);
        ctx[(size_t)r * Dc + d] = acc;
    }
}

// ---------------- VQ argmin over codebook ----------------
__global__ void vq_kernel(const float* __restrict__ x, const float* __restrict__ cb,
                          int* __restrict__ idx)
{
    __shared__ float mv[32];
    __shared__ float sd[256];
    __shared__ int   si[256];
    const int sb = blockIdx.x;
    const int s = sb >> 5, b = sb & 31;
    const int tid = threadIdx.x;
    if (tid < 32) mv[tid] = x[((size_t)b * Lc + s) * Zc + tid];
    __syncthreads();
    float bd = 3.4e38f; int bi = 0x7fffffff;
    for (int k = tid; k < KCB; k += 256) {
        const float* c = cb + (size_t)k * Zc;
        float d2 = 0.f;
#pragma unroll
        for (int z = 0; z < Zc; z++) { float df = mv[z] - c[z]; d2 = fmaf(df, df, d2); }
        if (d2 < bd || (d2 == bd && k < bi)) { bd = d2; bi = k; }
    }
    sd[tid] = bd; si[tid] = bi;
    __syncthreads();
    for (int off = 128; off; off >>= 1) {
        if (tid < off) {
            if (sd[tid + off] < sd[tid] ||
                (sd[tid + off] == sd[tid] && si[tid + off] < si[tid])) {
                sd[tid] = sd[tid + off]; si[tid] = si[tid + off];
            }
        }
        __syncthreads();
    }
    if (tid == 0) idx[sb] = si[0];
}

// ---------------- mem_h = codebook[idx] @ W_in + b_in  (bf16 pair out) ----------------
__global__ void build_memh_kernel(const float* __restrict__ cb, const int* __restrict__ idx,
                                  const float* __restrict__ Win, const float* __restrict__ bin,
                                  __nv_bfloat16* __restrict__ mh, __nv_bfloat16* __restrict__ ml)
{
    __shared__ float qv[32];
    const int sb = blockIdx.x;
    if (threadIdx.x < 32)
        qv[threadIdx.x] = cb[(size_t)idx[sb] * Zc + threadIdx.x];
    __syncthreads();
    for (int d = threadIdx.x; d < Dc; d += 128) {
        float acc = bin[d];
#pragma unroll
        for (int z = 0; z < Zc; z++)
            acc = fmaf(qv[z], Win[z * Dc + d], acc);
        __nv_bfloat16 h, l;
        split2(acc, h, l);
        mh[(size_t)sb * Dc + d] = h;
        ml[(size_t)sb * Dc + d] = l;
    }
}

// ---------------- init packed h from ctx + row->sb map + bf16 pair ----------------
__global__ void build_h_kernel(const float* __restrict__ ctx, float* __restrict__ h,
                               int* __restrict__ rowsb,
                               __nv_bfloat16* __restrict__ hh, __nv_bfloat16* __restrict__ hl)
{
    const int sb = blockIdx.x;
    const int s = sb >> 5, b = sb & 31;
    const int n = s + 1;
    const size_t base = row_base(s, b);
    const float* src = ctx + ((size_t)b * Lc) * Dc;
    float* dst = h + base * Dc;
    const int tot = n * Dc;
    for (int i = threadIdx.x; i < tot; i += 256) {
        float v = src[i];
        dst[i] = v;
        __nv_bfloat16 vh, vl;
        split2(v, vh, vl);
        hh[base * Dc + i] = vh;
        hl[base * Dc + i] = vl;
    }
    for (int l = threadIdx.x; l < n; l += 256)
        rowsb[base + l] = sb;
}

// ---------------- final readout ----------------
__global__ void final_kernel(const float* __restrict__ h,
                             const float* __restrict__ g, const float* __restrict__ bb,
                             const float* __restrict__ Wout, const float* __restrict__ bout,
                             float* __restrict__ out)
{
    __shared__ float red[8];
    __shared__ float tv[512];
    __shared__ float part[128];
    const int sb = blockIdx.x;
    const int s = sb >> 5, b = sb & 31;
    const int tid = threadIdx.x;
    const float* hr = h + (row_base(s, b) + s) * Dc;
    float x[4]; float sum = 0.f;
#pragma unroll
    for (int i = 0; i < 4; i++) { x[i] = hr[tid + i * 128]; sum += x[i]; }
#pragma unroll
    for (int o = 16; o; o >>= 1) sum += __shfl_xor_sync(0xffffffffu, sum, o);
    if ((tid & 31) == 0) red[tid >> 5] = sum;
    __syncthreads();
    float mean = (red[0] + red[1] + red[2] + red[3]) * (1.f / 512.f);
    float vs = 0.f;
#pragma unroll
    for (int i = 0; i < 4; i++) { float d = x[i] - mean; vs = fmaf(d, d, vs); }
#pragma unroll
    for (int o = 16; o; o >>= 1) vs += __shfl_xor_sync(0xffffffffu, vs, o);
    if ((tid & 31) == 0) red[4 + (tid >> 5)] = vs;
    __syncthreads();
    float var = (red[4] + red[5] + red[6] + red[7]) * (1.f / 512.f);
    float inv = rsqrtf(var + 1e-5f);
#pragma unroll
    for (int i = 0; i < 4; i++)
        tv[tid + i * 128] = (x[i] - mean) * inv * g[tid + i * 128] + bb[tid + i * 128];
    __syncthreads();
    const int z = tid & 31, c = tid >> 5;
    float acc = 0.f;
    for (int k = c * 128; k < c * 128 + 128; k++)
        acc = fmaf(tv[k], Wout[(size_t)k * Zc + z], acc);
    part[tid] = acc;
    __syncthreads();
    if (tid < 32)
        out[((size_t)b * Lc + s) * Zc + z] =
            part[z] + part[32 + z] + part[64 + z] + part[96 + z] + bout[z];
}

// ---------------- host helpers ----------------
static __nv_bfloat16 *s_wh, *s_wl;

static inline void wsplit(const float* W, int ldw, int col0, int rows, int cols)
{
    split_kernel<<<(rows * cols) / 256, 256>>>(W, ldw, col0, cols, s_wh, s_wl);
}

static inline void gemm(const __nv_bfloat16* Ah, const __nv_bfloat16* Al, int lda,
                        const float* bias, float* Cf,
                        __nv_bfloat16* Ch, __nv_bfloat16* Cl,
                        int ldc, int M, int N, int K, int relu)
{
    dim3 grid(N / 128, M / 128);
    mma_gemm_kernel<<<grid, 256, GEMM_SMEM>>>(Ah, Al, lda, s_wh, s_wl, N, bias,
                                              Cf, Ch, Cl, ldc, K, relu);
}

extern "C" void kernel_launch(void* const* d_in, const int* in_sizes, int n_in,
                              void* d_out, int out_size)
{
    const float* x        = (const float*)d_in[0];
    const float* codebook = (const float*)d_in[1];
    const float* W_in     = (const float*)d_in[2];
    const float* b_in     = (const float*)d_in[3];
    const float* sa_qkv_w = (const float*)d_in[4];
    const float* sa_qkv_b = (const float*)d_in[5];
    const float* sa_out_w = (const float*)d_in[6];
    const float* sa_out_b = (const float*)d_in[7];
    const float* ca_qkv_w = (const float*)d_in[8];
    const float* ca_qkv_b = (const float*)d_in[9];
    const float* ca_out_w = (const float*)d_in[10];
    const float* ca_out_b = (const float*)d_in[11];
    const float* ff1_w    = (const float*)d_in[12];
    const float* ff1_b    = (const float*)d_in[13];
    const float* ff2_w    = (const float*)d_in[14];
    const float* ff2_b    = (const float*)d_in[15];
    const float* ln1_g    = (const float*)d_in[16];
    const float* ln1_b    = (const float*)d_in[17];
    const float* ln2_g    = (const float*)d_in[18];
    const float* ln2_b    = (const float*)d_in[19];
    const float* ln3_g    = (const float*)d_in[20];
    const float* ln3_b    = (const float*)d_in[21];
    const float* ln_g     = (const float*)d_in[22];
    const float* ln_b     = (const float*)d_in[23];
    const float* W_out    = (const float*)d_in[24];
    const float* b_out    = (const float*)d_in[25];
    float* out = (float*)d_out;

    float *h, *big, *bf, *ctx, *cav; int *idx, *rowsb;
    __nv_bfloat16 *hh, *hl, *ah, *al, *fh, *fl, *mh, *ml, *vh, *vl;
    cudaGetSymbolAddress((void**)&h,    g_h);
    cudaGetSymbolAddress((void**)&big,  g_big);
    cudaGetSymbolAddress((void**)&bf,   g_bf);
    cudaGetSymbolAddress((void**)&ctx,  g_ctx);
    cudaGetSymbolAddress((void**)&cav,  g_cav);
    cudaGetSymbolAddress((void**)&idx,  g_idx);
    cudaGetSymbolAddress((void**)&rowsb, g_rowsb);
    cudaGetSymbolAddress((void**)&hh, g_hh);
    cudaGetSymbolAddress((void**)&hl, g_hl);
    cudaGetSymbolAddress((void**)&ah, g_ah);
    cudaGetSymbolAddress((void**)&al, g_al);
    cudaGetSymbolAddress((void**)&fh, g_fh);
    cudaGetSymbolAddress((void**)&fl, g_fl);
    cudaGetSymbolAddress((void**)&mh, g_mh);
    cudaGetSymbolAddress((void**)&ml, g_ml);
    cudaGetSymbolAddress((void**)&vh, g_vh);
    cudaGetSymbolAddress((void**)&vl, g_vl);
    cudaGetSymbolAddress((void**)&s_wh, g_wh);
    cudaGetSymbolAddress((void**)&s_wl, g_wl);

    cudaFuncSetAttribute(attn_kernel, cudaFuncAttributeMaxDynamicSharedMemorySize, ATTN_SMEM);
    cudaFuncSetAttribute(mma_gemm_kernel, cudaFuncAttributeMaxDynamicSharedMemorySize, GEMM_SMEM);

    build_ctx_kernel<<<SBc, 128>>>(x, W_in, b_in, ctx);
    vq_kernel<<<SBc, 256>>>(x, codebook, idx);
    build_memh_kernel<<<SBc, 128>>>(codebook, idx, W_in, b_in, mh, ml);
    build_h_kernel<<<SBc, 256>>>(ctx, h, rowsb, hh, hl);

    for (int l = 0; l < NLc; l++) {
        // --- self-attention ---
        wsplit(sa_qkv_w + (size_t)l * Dc * D3c, D3c, 0, Dc, D3c);
        gemm(hh, hl, Dc, sa_qkv_b + (size_t)l * D3c, big, 0, 0, D3c, ROWSE, D3c, Dc, 0);
        attn_kernel<<<dim3(SBc, Hc), 256, ATTN_SMEM>>>(big, ah, al);
        wsplit(sa_out_w + (size_t)l * Dc * Dc, Dc, 0, Dc, Dc);
        gemm(ah, al, Dc, sa_out_b + (size_t)l * Dc, bf, 0, 0, Dc, ROWSE, Dc, Dc, 0);
        ln_kernel<<<ROWSE, 128>>>(h, bf, ln1_g + (size_t)l * Dc, ln1_b + (size_t)l * Dc,
                                  rowsb, 0, hh, hl);

        // --- cross-attention: softmax over 1 key == identity -> value path only ---
        wsplit(ca_qkv_w + (size_t)l * Dc * D3c, D3c, 2 * Dc, Dc, Dc);
        gemm(mh, ml, Dc, ca_qkv_b + (size_t)l * D3c + 2 * Dc, 0, vh, vl, Dc, SBc, Dc, Dc, 0);
        wsplit(ca_out_w + (size_t)l * Dc * Dc, Dc, 0, Dc, Dc);
        gemm(vh, vl, Dc, ca_out_b + (size_t)l * Dc, cav, 0, 0, Dc, SBc, Dc, Dc, 0);
        ln_kernel<<<ROWSE, 128>>>(h, cav, ln2_g + (size_t)l * Dc, ln2_b + (size_t)l * Dc,
                                  rowsb, 1, hh, hl);

        // --- FFN ---
        wsplit(ff1_w + (size_t)l * Dc * DFFc, DFFc, 0, Dc, DFFc);
        gemm(hh, hl, Dc, ff1_b + (size_t)l * DFFc, 0, fh, fl, DFFc, ROWSE, DFFc, Dc, 1);
        wsplit(ff2_w + (size_t)l * DFFc * Dc, Dc, 0, DFFc, Dc);
        gemm(fh, fl, DFFc, ff2_b + (size_t)l * Dc, bf, 0, 0, Dc, ROWSE, Dc, DFFc, 0);
        ln_kernel<<<ROWSE, 128>>>(h, bf, ln3_g + (size_t)l * Dc, ln3_b + (size_t)l * Dc,
                                  rowsb, 0, hh, hl);
    }

    final_kernel<<<SBc, 128>>>(h, ln_g, ln_b, W_out, b_out, out);
}